// round 1
// baseline (speedup 1.0000x reference)
#include <cuda_runtime.h>
#include <cstddef>

#define NF 40
#define NE 64
#define NBATCH 4096
#define NP 780            // NF*(NF-1)/2
#define EV (NE/4)         // 16 float4 per pair
#define ROW_F4 (NP*EV)    // 12480 float4 per batch row
#define X_F4 (NF*EV)      // 640 float4 per x row
#define NTHREADS 512

// Shared layout: inter4[NP*EV] | xs4[X_F4] | pairs[NP]
#define SMEM_BYTES ((ROW_F4 + X_F4) * sizeof(float4) + NP * sizeof(unsigned))

__global__ __launch_bounds__(NTHREADS, 1)
void ffm_kernel(const float* __restrict__ x,
                const float* __restrict__ fe,
                float* __restrict__ out) {
    extern __shared__ char smem[];
    float4*   inter4 = (float4*)smem;
    float4*   xs4    = (float4*)(smem + (size_t)ROW_F4 * sizeof(float4));
    unsigned* pairs  = (unsigned*)(smem + (size_t)(ROW_F4 + X_F4) * sizeof(float4));

    const int tid = threadIdx.x;

    // --- pair index table: triu_indices(NF, k=1) row-major order ---
    for (int p = tid; p < NP; p += NTHREADS) {
        int i = 0, rem = p;
        while (rem >= NF - 1 - i) { rem -= NF - 1 - i; ++i; }
        int j = i + 1 + rem;
        pairs[p] = (unsigned)i | ((unsigned)j << 16);
    }
    __syncthreads();

    // --- inter[p][e] = fe[i,j,e] * fe[j,i,e], computed once per block ---
    const float4* fe4 = (const float4*)fe;
    for (int idx = tid; idx < ROW_F4; idx += NTHREADS) {
        int p = idx >> 4, w = idx & 15;
        unsigned pij = pairs[p];
        int i = (int)(pij & 0xffffu), j = (int)(pij >> 16);
        float4 a = fe4[(size_t)(i * NF + j) * EV + w];
        float4 b = fe4[(size_t)(j * NF + i) * EV + w];
        inter4[idx] = make_float4(a.x * b.x, a.y * b.y, a.z * b.z, a.w * b.w);
    }
    __syncthreads();

    // --- persistent loop over batch rows ---
    const float4* xg4 = (const float4*)x;
    for (int b = blockIdx.x; b < NBATCH; b += gridDim.x) {
        for (int v = tid; v < X_F4; v += NTHREADS)
            xs4[v] = xg4[(size_t)b * X_F4 + v];
        __syncthreads();

        float4* og4 = (float4*)out + (size_t)b * ROW_F4;
        #pragma unroll 4
        for (int idx = tid; idx < ROW_F4; idx += NTHREADS) {
            int p = idx >> 4, w = idx & 15;
            unsigned pij = pairs[p];
            int i = (int)(pij & 0xffffu), j = (int)(pij >> 16);
            float4 a = xs4[i * EV + w];
            float4 c = xs4[j * EV + w];
            float4 t = inter4[idx];
            og4[idx] = make_float4(a.x * c.x * t.x,
                                   a.y * c.y * t.y,
                                   a.z * c.z * t.z,
                                   a.w * c.w * t.w);
        }
        __syncthreads();
    }
}

extern "C" void kernel_launch(void* const* d_in, const int* in_sizes, int n_in,
                              void* d_out, int out_size) {
    const float* x  = (const float*)d_in[0];   // [B, F, E] float32
    const float* fe = (const float*)d_in[1];   // [F, F, E] float32
    float* out = (float*)d_out;                // [B, P*E] float32

    (void)in_sizes; (void)n_in; (void)out_size;

    cudaFuncSetAttribute(ffm_kernel,
                         cudaFuncAttributeMaxDynamicSharedMemorySize,
                         (int)SMEM_BYTES);

    int dev = 0, sms = 148;
    cudaGetDevice(&dev);
    cudaDeviceGetAttribute(&sms, cudaDevAttrMultiProcessorCount, dev);

    ffm_kernel<<<sms, NTHREADS, SMEM_BYTES>>>(x, fe, out);
}

// round 2
// speedup vs baseline: 1.2276x; 1.2276x over previous
#include <cuda_runtime.h>
#include <cstddef>

#define NF 40
#define NE 64
#define NBATCH 4096
#define NP 780                 // NF*(NF-1)/2
#define NPH 390                // pairs per CTA (half)
#define EV (NE/4)              // 16 float4 per pair
#define ROW_F4 (NP*EV)         // 12480 float4 per full output row
#define HROW_F4 (NPH*EV)       // 6240 float4 per CTA per row
#define X_F4 (NF*EV)           // 640 float4 per x row
#define NTHREADS 512

// Shared layout per CTA: inter4[HROW_F4] | xs4[X_F4] | pairs[NPH]
#define SMEM_BYTES ((HROW_F4 + X_F4) * sizeof(float4) + NPH * sizeof(unsigned))

__global__ __launch_bounds__(NTHREADS, 2)
void ffm_kernel(const float* __restrict__ x,
                const float* __restrict__ fe,
                float* __restrict__ out) {
    extern __shared__ char smem[];
    float4*   inter4 = (float4*)smem;
    float4*   xs4    = (float4*)(smem + (size_t)HROW_F4 * sizeof(float4));
    unsigned* pairs  = (unsigned*)(smem + (size_t)(HROW_F4 + X_F4) * sizeof(float4));

    const int tid  = threadIdx.x;
    const int half = blockIdx.x & 1;        // which pair-half this CTA owns
    const int pbase = half * NPH;

    // --- local pair table: triu_indices(NF, k=1), global pairs [pbase, pbase+NPH) ---
    for (int p = tid; p < NPH; p += NTHREADS) {
        int pg = p + pbase;
        int i = 0, rem = pg;
        while (rem >= NF - 1 - i) { rem -= NF - 1 - i; ++i; }
        int j = i + 1 + rem;
        pairs[p] = (unsigned)i | ((unsigned)j << 16);
    }
    __syncthreads();

    // --- inter[p][e] = fe[i,j,e] * fe[j,i,e], once per CTA ---
    const float4* fe4 = (const float4*)fe;
    for (int idx = tid; idx < HROW_F4; idx += NTHREADS) {
        int p = idx >> 4, w = idx & 15;
        unsigned pij = pairs[p];
        int i = (int)(pij & 0xffffu), j = (int)(pij >> 16);
        float4 a = fe4[(size_t)(i * NF + j) * EV + w];
        float4 b = fe4[(size_t)(j * NF + i) * EV + w];
        inter4[idx] = make_float4(a.x * b.x, a.y * b.y, a.z * b.z, a.w * b.w);
    }

    // --- persistent loop over batch rows, register-prefetched x ---
    const float4* xg4 = (const float4*)x;
    const int b0      = blockIdx.x >> 1;
    const int bstride = gridDim.x >> 1;

    float4 r0 = make_float4(0.f, 0.f, 0.f, 0.f);
    float4 r1 = r0;
    if (b0 < NBATCH) {
        r0 = xg4[(size_t)b0 * X_F4 + tid];                    // tid < 512 < 640
        if (tid < X_F4 - NTHREADS) r1 = xg4[(size_t)b0 * X_F4 + tid + NTHREADS];
    }

    for (int b = b0; b < NBATCH; b += bstride) {
        __syncthreads();                 // previous row's readers done (also fences inter init)
        xs4[tid] = r0;
        if (tid < X_F4 - NTHREADS) xs4[tid + NTHREADS] = r1;

        int bn = b + bstride;            // prefetch next row while we compute this one
        if (bn < NBATCH) {
            r0 = xg4[(size_t)bn * X_F4 + tid];
            if (tid < X_F4 - NTHREADS) r1 = xg4[(size_t)bn * X_F4 + tid + NTHREADS];
        }
        __syncthreads();                 // xs4 ready

        float4* og4 = (float4*)out + (size_t)b * ROW_F4 + (size_t)half * HROW_F4;
        #pragma unroll 4
        for (int idx = tid; idx < HROW_F4; idx += NTHREADS) {
            int p = idx >> 4, w = idx & 15;
            unsigned pij = pairs[p];
            int i = (int)(pij & 0xffffu), j = (int)(pij >> 16);
            float4 a = xs4[i * EV + w];
            float4 c = xs4[j * EV + w];
            float4 t = inter4[idx];
            float4 v = make_float4(a.x * c.x * t.x,
                                   a.y * c.y * t.y,
                                   a.z * c.z * t.z,
                                   a.w * c.w * t.w);
            __stcs(&og4[idx], v);        // streaming store: write-only, evict-first
        }
    }
}

extern "C" void kernel_launch(void* const* d_in, const int* in_sizes, int n_in,
                              void* d_out, int out_size) {
    const float* x  = (const float*)d_in[0];   // [B, F, E] float32
    const float* fe = (const float*)d_in[1];   // [F, F, E] float32
    float* out = (float*)d_out;                // [B, P*E] float32

    (void)in_sizes; (void)n_in; (void)out_size;

    cudaFuncSetAttribute(ffm_kernel,
                         cudaFuncAttributeMaxDynamicSharedMemorySize,
                         (int)SMEM_BYTES);

    int dev = 0, sms = 148;
    cudaGetDevice(&dev);
    cudaDeviceGetAttribute(&sms, cudaDevAttrMultiProcessorCount, dev);

    ffm_kernel<<<2 * sms, NTHREADS, SMEM_BYTES>>>(x, fe, out);
}